// round 8
// baseline (speedup 1.0000x reference)
#include <cuda_runtime.h>
#include <cuda.h>
#include <cstdint>

// ConstituencyMFVI: B=8, N=192, 3 mean-field iterations.
// q[b,i,j] = s_span[b,i,j] + (j>i) * sum_{k != i, k != j} sigmoid(q[b,i,k]) * s_pair[b,i,j,k]
// out = sigmoid(q).
//
// R8: persistent-CTA cross-tile pipeline. 148 CTAs (occ 1, 192 threads), each
// owns ~10.4 (b,i) tiles ranked by size (g = i*8+b dealt round-robin -> ~equal
// bytes/CTA). Three 73.7KB SMEM half-tile buffers rotate: while tile n computes
// (low half in 96 regs, high half in SMEM buffer), TMA streams tile n+1's two
// halves into the other buffers -> the DRAM stream never stops. Rows j<=i are
// never loaded (mask analytic): 113MB total HBM. OOB rows zero-filled by TMA.

namespace {
constexpr int NN      = 192;
constexpr int HALF    = 96;
constexpr int CH      = 24;                       // float4 chunks per half row
constexpr int BOXROWS = 48;
constexpr int BOXBYTES = BOXROWS * HALF * 4;      // 18432
constexpr int THREADS = 192;
constexpr int NSM     = 148;
constexpr int NTILES  = NN * 8;                   // 1536
constexpr int HB      = NN * HALF;                // floats per half buffer
constexpr int SMEM_BYTES = 3 * HB * 4 + NN * 4 + 3 * 8;  // 221976
}

__device__ __forceinline__ float sigmoidf(float x) {
    return 1.0f / (1.0f + __expf(-x));
}
__device__ __forceinline__ void mbar_init(uint32_t a, uint32_t cnt) {
    asm volatile("mbarrier.init.shared.b64 [%0], %1;\n" :: "r"(a), "r"(cnt) : "memory");
}
__device__ __forceinline__ void mbar_expect_tx(uint32_t a, uint32_t bytes) {
    asm volatile("mbarrier.arrive.expect_tx.shared.b64 _, [%0], %1;\n" :: "r"(a), "r"(bytes) : "memory");
}
__device__ __forceinline__ void mbar_wait(uint32_t a, int parity) {
    asm volatile("{\n\t"
                 ".reg .pred P;\n\t"
                 "WL_%=:\n\t"
                 "mbarrier.try_wait.parity.acquire.cta.shared::cta.b64 P, [%0], %1, 0x989680;\n\t"
                 "@P bra.uni WD_%=;\n\t"
                 "bra.uni WL_%=;\n\t"
                 "WD_%=:\n\t"
                 "}\n" :: "r"(a), "r"(parity) : "memory");
}
__device__ __forceinline__ void tma_load3d(uint32_t dst, const CUtensorMap* m,
                                           int x, int y, int z, uint32_t mbar) {
    asm volatile("cp.async.bulk.tensor.3d.shared::cta.global.tile.mbarrier::complete_tx::bytes "
                 "[%0], [%1, {%2, %3, %4}], [%5];\n"
                 :: "r"(dst), "l"(m), "r"(x), "r"(y), "r"(z), "r"(mbar) : "memory");
}

// issue one half (xoff = 0 or 96) of tile (b,i) into the buffer at sbuf.
// nb==0 (R==0) -> no-op; waits are guarded by the same condition.
__device__ __forceinline__ void issue_half(uint32_t sbuf, uint32_t mbar,
                                           const CUtensorMap* tm, int xoff,
                                           int i, int tz) {
    int R  = NN - 1 - i;
    int nb = (R + BOXROWS - 1) / BOXROWS;
    if (nb <= 0) return;
    asm volatile("fence.proxy.async.shared::cta;\n" ::: "memory");
    mbar_expect_tx(mbar, (uint32_t)(nb * BOXBYTES));
    for (int bi = 0; bi < nb; bi++)
        tma_load3d(sbuf + bi * BOXROWS * HALF * 4, tm,
                   xoff, i + 1 + bi * BOXROWS, tz, mbar);
}

__global__ __launch_bounds__(THREADS, 1)
void mfvi_kernel(const __grid_constant__ CUtensorMap tmap,
                 const float* __restrict__ s_span,
                 float* __restrict__ out)
{
    extern __shared__ float smf[];
    float* bufs = smf;                 // 3 x [192 rows][96 floats]
    float* sig  = smf + 3 * HB;        // [192]
    const uint32_t sb0   = (uint32_t)__cvta_generic_to_shared(smf);
    const uint32_t smbar = sb0 + (uint32_t)(3 * HB + NN) * 4u;

    const int s = blockIdx.x;
    const int t = threadIdx.x;
    const int m = (NTILES - s + NSM - 1) / NSM;   // tiles for this CTA (10 or 11)
    const int rot = t % CH;

    if (t == 0) { mbar_init(smbar, 1); mbar_init(smbar + 8, 1); mbar_init(smbar + 16, 1); }
    __syncthreads();

    // g -> (b,i): g = i*8+b (R-descending rank). tz = b*192+i indexes memory.
    auto g_of   = [&](int n) { return s + n * NSM; };

    // ---- prologue: low(0)->buf0, high(0)->buf1, low(1)->buf2 ----
    if (t == 0) {
        { int g = g_of(0); int i = g >> 3, b = g & 7, tz = b * NN + i;
          issue_half(sb0 + 0 * HB * 4, smbar + 0,  &tmap, 0,    i, tz);
          issue_half(sb0 + 1 * HB * 4, smbar + 8,  &tmap, HALF, i, tz); }
        if (m > 1) { int g = g_of(1); int i = g >> 3, b = g & 7, tz = b * NN + i;
          issue_half(sb0 + 2 * HB * 4, smbar + 16, &tmap, 0,    i, tz); }
    }

    int ph[3] = {0, 0, 0};
    float4 r[CH];

    for (int n = 0; n < m; n++) {
        const int g  = g_of(n);
        const int i  = g >> 3;
        const int b  = g & 7;
        const int tz = b * NN + i;
        const int R  = NN - 1 - i;
        const bool valid = t < R;
        const int j  = i + 1 + t;
        const float* gs = s_span + (size_t)tz * NN;

        const int bl = (2 * n) % 3;
        const int bh = (2 * n + 1) % 3;

        // sig + constant outputs for this tile (prev tile's reads done: see
        // trailing __syncthreads below)
        if (t <= i) { float v = sigmoidf(gs[t]); sig[t] = v; out[(size_t)tz * NN + t] = v; }
        float sv = 0.0f;
        if (valid) { sv = gs[j]; sig[j] = sigmoidf(sv); }

        if (R > 0) {
            mbar_wait(smbar + 8 * bl, ph[bl]); ph[bl] ^= 1;
            if (valid) {
                float* myrow = bufs + bl * HB + t * HALF;
                if (i < HALF) myrow[i] = 0.0f;       // k == i
                if (j < HALF) myrow[j] = 0.0f;       // k == j
                const float4* row4 = reinterpret_cast<const float4*>(myrow);
                #pragma unroll
                for (int cc = 0; cc < CH; cc++) {
                    int idx = rot + cc; if (idx >= CH) idx -= CH;
                    r[cc] = row4[idx];               // r[cc] holds chunk idx
                }
            }
        }
        __syncthreads();   // reg copies + sig publishes complete CTA-wide

        // buffer bl is free -> stream high(n+1) into it, overlapping compute(n)
        if (t == 0 && n + 1 < m) {
            int g1 = g_of(n + 1); int i1 = g1 >> 3, b1 = g1 & 7;
            issue_half(sb0 + bl * HB * 4, smbar + 8 * bl, &tmap, HALF, i1, b1 * NN + i1);
        }

        if (R > 0) {
            mbar_wait(smbar + 8 * bh, ph[bh]); ph[bh] ^= 1;
            if (valid) {                             // zero excluded high-half entries
                float* myrowH = bufs + bh * HB + t * HALF;
                if (i >= HALF) myrowH[i - HALF] = 0.0f;
                if (j >= HALF) myrowH[j - HALF] = 0.0f;
            }

            const float4* row4 = reinterpret_cast<const float4*>(bufs + bh * HB + t * HALF);
            const float4* sig4 = reinterpret_cast<const float4*>(sig);
            float q = sv;

            #pragma unroll 1
            for (int it = 0; it < 3; it++) {
                if (valid) {
                    float ax = 0.f, ay = 0.f, az = 0.f, aw = 0.f;
                    #pragma unroll
                    for (int cc = 0; cc < CH; cc++) {        // low half: regs
                        int idx = rot + cc; if (idx >= CH) idx -= CH;
                        float4 sg = sig4[idx];
                        ax = fmaf(r[cc].x, sg.x, ax);
                        ay = fmaf(r[cc].y, sg.y, ay);
                        az = fmaf(r[cc].z, sg.z, az);
                        aw = fmaf(r[cc].w, sg.w, aw);
                    }
                    #pragma unroll
                    for (int cc = 0; cc < CH; cc++) {        // high half: SMEM (rotated)
                        int idx = rot + cc; if (idx >= CH) idx -= CH;
                        float4 p  = row4[idx];
                        float4 sg = sig4[CH + idx];
                        ax = fmaf(p.x, sg.x, ax);
                        ay = fmaf(p.y, sg.y, ay);
                        az = fmaf(p.z, sg.z, az);
                        aw = fmaf(p.w, sg.w, aw);
                    }
                    q = sv + ((ax + ay) + (az + aw));
                }
                if (it < 2) {
                    __syncthreads();                 // all sig reads done
                    if (valid) sig[j] = sigmoidf(q);
                    __syncthreads();
                }
            }
            if (valid) out[(size_t)tz * NN + j] = sigmoidf(q);
        }
        __syncthreads();   // all reads of buffer bh + sig done

        // buffer bh is free -> stream low(n+2) into it
        if (t == 0 && n + 2 < m) {
            int g2 = g_of(n + 2); int i2 = g2 >> 3, b2 = g2 & 7;
            issue_half(sb0 + bh * HB * 4, smbar + 8 * bh, &tmap, 0, i2, b2 * NN + i2);
        }
    }
}

// --------------------------------------------------------------------------

typedef CUresult (*PFN_tmapEncode)(
    CUtensorMap*, CUtensorMapDataType, cuuint32_t, void*,
    const cuuint64_t*, const cuuint64_t*, const cuuint32_t*, const cuuint32_t*,
    CUtensorMapInterleave, CUtensorMapSwizzle, CUtensorMapL2promotion,
    CUtensorMapFloatOOBfill);

extern "C" void kernel_launch(void* const* d_in, const int* in_sizes, int n_in,
                              void* d_out, int out_size)
{
    const float* s_span = (const float*)d_in[0];
    void*        s_pair = (void*)d_in[1];
    float* out = (float*)d_out;

    PFN_tmapEncode pfn = nullptr;
    cudaDriverEntryPointQueryResult qres;
    cudaGetDriverEntryPoint("cuTensorMapEncodeTiled", (void**)&pfn,
                            cudaEnableDefault, &qres);

    CUtensorMap tmap;
    cuuint64_t dims[3]    = {NN, NN, (cuuint64_t)NTILES};
    cuuint64_t strides[2] = {(cuuint64_t)NN * 4, (cuuint64_t)NN * NN * 4};
    cuuint32_t box[3]     = {HALF, BOXROWS, 1};
    cuuint32_t estr[3]    = {1, 1, 1};
    pfn(&tmap, CU_TENSOR_MAP_DATA_TYPE_FLOAT32, 3, s_pair,
        dims, strides, box, estr,
        CU_TENSOR_MAP_INTERLEAVE_NONE, CU_TENSOR_MAP_SWIZZLE_NONE,
        CU_TENSOR_MAP_L2_PROMOTION_L2_128B, CU_TENSOR_MAP_FLOAT_OOB_FILL_NONE);

    cudaFuncSetAttribute(mfvi_kernel,
                         cudaFuncAttributeMaxDynamicSharedMemorySize, SMEM_BYTES);

    mfvi_kernel<<<NSM, THREADS, SMEM_BYTES>>>(tmap, s_span, out);
}

// round 9
// speedup vs baseline: 1.5103x; 1.5103x over previous
#include <cuda_runtime.h>
#include <cstdint>

// ConstituencyMFVI: B=8, N=192, 3 mean-field iterations.
// q[b,i,j] = s_span[b,i,j] + (j>i) * sum_{k != i, k != j} sigmoid(q[b,i,k]) * s_pair[b,i,j,k]
// out = sigmoid(q).
//
// R9: persistent CTAs + cp.async cross-tile pipeline.
// 148 persistent CTAs (1/SM), 384 threads (12 warps -> max cp.async in-flight
// at occ 1). Each CTA processes ~10.4 (b,i) tiles, size-rank dealt. Three
// 192x100 padded half-tile SMEM buffers rotate so the next tile's halves
// stream in (cp.async, coalesced, issued by all 12 warps) while the current
// tile computes -> the DRAM stream never stops. Threads 0..191 (h0) cache the
// low k-half of their row in 24xfloat4 regs and FMA from regs; threads
// 192..383 (h1) FMA the high half from SMEM; partial dots joined via SMEM.
// Rows j<=i never loaded (mask analytic): 113MB total HBM.
// Pipeline sync: every loop commits exactly 2 cp.async groups (empty commits
// keep per-thread counts uniform) => a single `cp.async.wait_group 2` pins
// each buffer.

namespace {
constexpr int NN      = 192;
constexpr int HALF    = 96;
constexpr int CH      = 24;          // float4 chunks per half row
constexpr int PADH    = 100;         // half-row stride (100%8==4 -> conflict-free LDS.128)
constexpr int THREADS = 384;
constexpr int NSM     = 148;
constexpr int NTILES  = 1536;
constexpr int HB      = NN * PADH;   // floats per half buffer (19200)
constexpr int SMEM_BYTES = (3 * HB + 2 * NN) * 4;   // 231,936
}

__device__ __forceinline__ float sigmoidf(float x) {
    return 1.0f / (1.0f + __expf(-x));
}

__global__ __launch_bounds__(THREADS, 1)
void mfvi_kernel(const float* __restrict__ s_span,
                 const float* __restrict__ s_pair,
                 float* __restrict__ out)
{
    extern __shared__ float smf[];
    float* bufs = smf;                 // 3 x [192][PADH]
    float* sig  = smf + 3 * HB;        // [192]
    float* part = sig + NN;            // [192]

    const int s  = blockIdx.x;
    const int t  = threadIdx.x;
    const bool h0 = t < NN;
    const int jj = h0 ? t : t - NN;    // my row index (global j)
    const int m  = (NTILES - s + NSM - 1) / NSM;   // 10 or 11 tiles

    const int rr0 = t / CH;            // 0..15  (384 = 16 rows x 24 chunks)
    const int cc0 = t % CH;

    // issue one half (xoff 0 or 96) of tile n into buffer `bi`; ALWAYS commits
    // exactly one group (empty if n out of range or R==0).
    auto issue_half = [&](int bi, int n, int xoff) {
        if (n < m) {
            int g  = s + n * NSM;
            int i  = g >> 3;
            int R  = NN - 1 - i;
            const float* gP = s_pair + (size_t)((g & 7) * NN + i) * (NN * NN);
            uint32_t sb = (uint32_t)__cvta_generic_to_shared(bufs + bi * HB);
            for (int rr = rr0; rr < R; rr += 16) {
                int row = i + 1 + rr;
                uint32_t dst = sb + (uint32_t)(row * PADH + cc0 * 4) * 4u;
                const float* src = gP + (size_t)row * NN + xoff + cc0 * 4;
                asm volatile("cp.async.cg.shared.global [%0], [%1], 16;\n"
                             :: "r"(dst), "l"(src));
            }
        }
        asm volatile("cp.async.commit_group;\n");
    };

    // ---- prologue: L0 -> buf0, H0 -> buf1, L1 -> buf2  (3 groups) ----
    issue_half(0, 0, 0);
    issue_half(1, 0, HALF);
    issue_half(2, 1, 0);

    float4 r[CH];

    for (int n = 0; n < m; n++) {
        const int g  = s + n * NSM;
        const int i  = g >> 3;
        const int tz = (g & 7) * NN + i;
        const int bl = (2 * n) % 3;
        const int bh = (2 * n + 1) % 3;
        const bool act = jj > i;

        // ---- low(n) resident ----
        asm volatile("cp.async.wait_group 2;\n");
        __syncthreads();

        float sv = 0.0f;
        if (h0) {
            float sval = s_span[(size_t)tz * NN + t];
            if (t <= i) {                       // constant rows: sigma fixed
                float v = sigmoidf(sval);
                sig[t] = v;
                out[(size_t)tz * NN + t] = v;
            } else {
                sv = sval;
                sig[t] = sigmoidf(sv);          // sigma^0 of my active row
                float* rowp = bufs + bl * HB + t * PADH;
                if (i < HALF) rowp[i] = 0.0f;   // k == i exclusion
                if (t < HALF) rowp[t] = 0.0f;   // k == j exclusion
                const float4* r4 = reinterpret_cast<const float4*>(rowp);
                #pragma unroll
                for (int c = 0; c < CH; c++) r[c] = r4[c];
            }
        }
        __syncthreads();                        // reg copies + sig publishes done

        issue_half(bl, n + 1, HALF);            // high(n+1) into freed bl

        // ---- high(n) resident ----
        asm volatile("cp.async.wait_group 2;\n");
        __syncthreads();

        const float4* sig4 = reinterpret_cast<const float4*>(sig);
        float* rowpH = bufs + bh * HB + jj * PADH;

        #pragma unroll 1
        for (int it = 0; it < 3; it++) {
            float p0 = 0.0f;
            if (!h0 && act) {                   // high half from SMEM
                if (it == 0) {
                    if (i  >= HALF) rowpH[i  - HALF] = 0.0f;
                    if (jj >= HALF) rowpH[jj - HALF] = 0.0f;
                }
                const float4* p4 = reinterpret_cast<const float4*>(rowpH);
                float ax = 0.f, ay = 0.f, az = 0.f, aw = 0.f;
                #pragma unroll
                for (int c = 0; c < CH; c++) {
                    float4 p  = p4[c];
                    float4 sg = sig4[CH + c];
                    ax = fmaf(p.x, sg.x, ax);
                    ay = fmaf(p.y, sg.y, ay);
                    az = fmaf(p.z, sg.z, az);
                    aw = fmaf(p.w, sg.w, aw);
                }
                part[jj] = (ax + ay) + (az + aw);
            }
            if (h0 && act) {                    // low half from regs
                float ax = 0.f, ay = 0.f, az = 0.f, aw = 0.f;
                #pragma unroll
                for (int c = 0; c < CH; c++) {
                    float4 sg = sig4[c];
                    ax = fmaf(r[c].x, sg.x, ax);
                    ay = fmaf(r[c].y, sg.y, ay);
                    az = fmaf(r[c].z, sg.z, az);
                    aw = fmaf(r[c].w, sg.w, aw);
                }
                p0 = (ax + ay) + (az + aw);
            }
            __syncthreads();                    // part[] published
            if (h0 && act) {
                float q = sv + p0 + part[t];
                if (it < 2) sig[t] = sigmoidf(q);
                else        out[(size_t)tz * NN + t] = sigmoidf(q);
            }
            __syncthreads();                    // sig stable / part reusable
        }

        issue_half(bh, n + 2, 0);               // low(n+2) into freed bh
    }
}

extern "C" void kernel_launch(void* const* d_in, const int* in_sizes, int n_in,
                              void* d_out, int out_size)
{
    const float* s_span = (const float*)d_in[0];
    const float* s_pair = (const float*)d_in[1];
    float* out = (float*)d_out;

    cudaFuncSetAttribute(mfvi_kernel,
                         cudaFuncAttributeMaxDynamicSharedMemorySize, SMEM_BYTES);

    mfvi_kernel<<<NSM, THREADS, SMEM_BYTES>>>(s_span, s_pair, out);
}